// round 2
// baseline (speedup 1.0000x reference)
#include <cuda_runtime.h>
#include <cuda_bf16.h>
#include <cstddef>

// Problem constants
#define D_MODEL 2048
#define SEQ     2048
#define BATCH   2
#define NH      16
#define HD      128
#define MROWS   (BATCH * SEQ)          // 4096
#define QKV_N   (3 * D_MODEL)          // 6144

// Scratch (allocation-guard safe: __device__ globals, bss)
__device__ float g_qkv[(size_t)MROWS * QKV_N];   // (b*s, 3*d_model)
__device__ float g_att[(size_t)MROWS * D_MODEL]; // (b*s, d_model), head-contiguous

// ---------------------------------------------------------------------------
// SGEMM + bias: C[M,N] = A[M,K] @ B[K,N] + bias[N]
// 128x128 block tile, BK=8, 256 threads, 8x8 micro-tile per thread split as
// {4 rows, 4 rows+64} x {4 cols, 4 cols+64} for conflict-free LDS.128.
// Double-buffered smem; gmem prefetch to registers overlaps compute.
// Requires M,N multiples of 128, K multiple of 8 (true for all GEMMs here).
// ---------------------------------------------------------------------------
__global__ __launch_bounds__(256, 2) void sgemm128(
    const float* __restrict__ A, const float* __restrict__ B,
    const float* __restrict__ bias, float* __restrict__ C,
    int M, int N, int K)
{
    __shared__ float As[2][8][132];   // [buf][k][m], padded stride kills store conflicts
    __shared__ float Bs[2][8][128];   // [buf][k][n]

    const int t = threadIdx.x;
    const int row0 = blockIdx.y * 128;
    const int col0 = blockIdx.x * 128;

    // gmem load assignment: A -> one float4/thread (128 rows x 8k),
    //                       B -> one float4/thread (8k x 128 cols)
    const int arow  = t >> 1;          // 0..127
    const int akcol = (t & 1) << 2;    // 0 or 4
    const int bkrow = t >> 5;          // 0..7
    const int bcol  = (t & 31) << 2;   // 0..124

    const float* Aptr = A + (size_t)(row0 + arow) * K + akcol;
    const float* Bptr = B + (size_t)bkrow * N + col0 + bcol;

    // compute assignment: rows {tm, tm+64}+0..3 , cols {tn, tn+64}+0..3
    const int tm = (t >> 4) << 2;      // 0,4,...,60
    const int tn = (t & 15) << 2;      // 0,4,...,60

    float acc[8][8];
#pragma unroll
    for (int i = 0; i < 8; i++)
#pragma unroll
        for (int j = 0; j < 8; j++) acc[i][j] = 0.f;

    // preload first k-slab into buffer 0
    float4 av = *(const float4*)(Aptr);
    float4 bv = *(const float4*)(Bptr);
    As[0][akcol + 0][arow] = av.x;
    As[0][akcol + 1][arow] = av.y;
    As[0][akcol + 2][arow] = av.z;
    As[0][akcol + 3][arow] = av.w;
    *(float4*)&Bs[0][bkrow][bcol] = bv;
    __syncthreads();

    for (int k0 = 0; k0 < K; k0 += 8) {
        const int buf = (k0 >> 3) & 1;
        const bool more = (k0 + 8) < K;
        if (more) {   // prefetch next slab to registers (latency hidden by FFMAs)
            av = *(const float4*)(Aptr + k0 + 8);
            bv = *(const float4*)(Bptr + (size_t)(k0 + 8) * N);
        }

#pragma unroll
        for (int kk = 0; kk < 8; kk++) {
            float a[8], b[8];
            *(float4*)&a[0] = *(const float4*)&As[buf][kk][tm];
            *(float4*)&a[4] = *(const float4*)&As[buf][kk][tm + 64];
            *(float4*)&b[0] = *(const float4*)&Bs[buf][kk][tn];
            *(float4*)&b[4] = *(const float4*)&Bs[buf][kk][tn + 64];
#pragma unroll
            for (int i = 0; i < 8; i++)
#pragma unroll
                for (int j = 0; j < 8; j++)
                    acc[i][j] += a[i] * b[j];
        }

        if (more) {   // stage into the other buffer, then one sync per slab
            const int nbuf = buf ^ 1;
            As[nbuf][akcol + 0][arow] = av.x;
            As[nbuf][akcol + 1][arow] = av.y;
            As[nbuf][akcol + 2][arow] = av.z;
            As[nbuf][akcol + 3][arow] = av.w;
            *(float4*)&Bs[nbuf][bkrow][bcol] = bv;
            __syncthreads();
        }
    }

    // epilogue: bias + store (rows {tm,tm+64}+i, col groups tn and tn+64)
    const float4 bb0 = *(const float4*)(bias + col0 + tn);
    const float4 bb1 = *(const float4*)(bias + col0 + tn + 64);
#pragma unroll
    for (int i = 0; i < 8; i++) {
        const int row = row0 + ((i < 4) ? (tm + i) : (tm + 64 + (i - 4)));
        float* crow = C + (size_t)row * N + col0;
        float4 o0, o1;
        o0.x = acc[i][0] + bb0.x; o0.y = acc[i][1] + bb0.y;
        o0.z = acc[i][2] + bb0.z; o0.w = acc[i][3] + bb0.w;
        o1.x = acc[i][4] + bb1.x; o1.y = acc[i][5] + bb1.y;
        o1.z = acc[i][6] + bb1.z; o1.w = acc[i][7] + bb1.w;
        *(float4*)(crow + tn)      = o0;
        *(float4*)(crow + tn + 64) = o1;
    }
}

// ---------------------------------------------------------------------------
// Causal flash attention, fp32.
// grid: (SEQ/64, BATCH*NH), block: 256 threads.
// Thread t owns q-row r = t/4 and key-chunk / d-chunk c = t%4.
//   S pass : thread computes S[r, c*16 .. c*16+15] (full 128-d dots).
//   PV pass: thread accumulates O[r, c*32 .. c*32+31].
// Online softmax stats (m, l) kept redundantly in the 4 lanes of a row group
// (consecutive lanes -> shfl_xor 1,2 reductions).
// ---------------------------------------------------------------------------
#define ATT_QS_STRIDE 132
#define ATT_PS_STRIDE 68
#define ATT_SMEM_FLOATS (3 * 64 * ATT_QS_STRIDE + 64 * ATT_PS_STRIDE)
#define ATT_SMEM_BYTES  (ATT_SMEM_FLOATS * 4)

__global__ __launch_bounds__(256) void attn_kernel(
    const float* __restrict__ qkv, float* __restrict__ att)
{
    extern __shared__ float smem[];
    float* Qs = smem;                        // 64 x 132
    float* Ks = Qs + 64 * ATT_QS_STRIDE;     // 64 x 132
    float* Vs = Ks + 64 * ATT_QS_STRIDE;     // 64 x 132
    float* Ps = Vs + 64 * ATT_QS_STRIDE;     // 64 x 68

    const int t = threadIdx.x;
    const int r = t >> 2;        // q row within tile (0..63)
    const int c = t & 3;         // chunk id (0..3)
    const int bh = blockIdx.y;
    const int b  = bh >> 4;
    const int h  = bh & 15;
    const int q0 = blockIdx.x * 64;

    const float* base = qkv + (size_t)b * SEQ * QKV_N + (size_t)h * HD;

    // Load Q tile (64 x 128): 2048 float4, 8 per thread, coalesced.
    for (int i = t; i < 64 * 32; i += 256) {
        const int row = i >> 5;
        const int col = (i & 31) << 2;
        const float4 v = *(const float4*)(base + (size_t)(q0 + row) * QKV_N + col);
        *(float4*)&Qs[row * ATT_QS_STRIDE + col] = v;
    }

    float o[32];
#pragma unroll
    for (int i = 0; i < 32; i++) o[i] = 0.f;
    float m = -1e30f, l = 0.f;

    const float scale = 0.08838834764831845f;   // 1/sqrt(128)
    const int ntiles = blockIdx.x + 1;          // causal: only k-tiles <= q-tile

    for (int kt = 0; kt < ntiles; kt++) {
        // Load K and V tiles
        for (int i = t; i < 64 * 32; i += 256) {
            const int row = i >> 5;
            const int col = (i & 31) << 2;
            const size_t roff = (size_t)(kt * 64 + row) * QKV_N;
            const float4 kv = *(const float4*)(base + roff + D_MODEL + col);
            const float4 vv = *(const float4*)(base + roff + 2 * D_MODEL + col);
            *(float4*)&Ks[row * ATT_QS_STRIDE + col] = kv;
            *(float4*)&Vs[row * ATT_QS_STRIDE + col] = vv;
        }
        __syncthreads();   // also covers Qs on first iteration

        // S[r, c*16+j] = Q[r,:] . K[c*16+j,:]
        float s[16];
#pragma unroll
        for (int j = 0; j < 16; j++) s[j] = 0.f;
        const float* qrow = &Qs[r * ATT_QS_STRIDE];
        const float* krow0 = &Ks[(c * 16) * ATT_QS_STRIDE];
#pragma unroll 4
        for (int d = 0; d < HD; d += 4) {
            const float4 qv = *(const float4*)(qrow + d);
#pragma unroll
            for (int j = 0; j < 16; j++) {
                const float4 kv = *(const float4*)(krow0 + j * ATT_QS_STRIDE + d);
                s[j] += qv.x * kv.x + qv.y * kv.y + qv.z * kv.z + qv.w * kv.w;
            }
        }

        // scale + causal mask
        const int qg = q0 + r;
#pragma unroll
        for (int j = 0; j < 16; j++) {
            const int kg = kt * 64 + c * 16 + j;
            s[j] = (kg > qg) ? -1e30f : s[j] * scale;
        }

        // row max across this thread's 16 keys, then across the 4-lane group
        float mt = s[0];
#pragma unroll
        for (int j = 1; j < 16; j++) mt = fmaxf(mt, s[j]);
        mt = fmaxf(mt, __shfl_xor_sync(0xffffffffu, mt, 1));
        mt = fmaxf(mt, __shfl_xor_sync(0xffffffffu, mt, 2));

        const float mnew  = fmaxf(m, mt);
        const float alpha = __expf(m - mnew);

        float lsum = 0.f;
        float* prow = &Ps[r * ATT_PS_STRIDE + c * 16];
#pragma unroll
        for (int j = 0; j < 16; j++) {
            const float p = __expf(s[j] - mnew);
            lsum += p;
            prow[j] = p;
        }
        lsum += __shfl_xor_sync(0xffffffffu, lsum, 1);
        lsum += __shfl_xor_sync(0xffffffffu, lsum, 2);

        l = l * alpha + lsum;
        m = mnew;
#pragma unroll
        for (int i = 0; i < 32; i++) o[i] *= alpha;

        __syncthreads();   // Ps visible to all lanes of each row group

        // O[r, c*32 + 0..31] += P[r, k] * V[k, c*32 + 0..31]
        const float* pr = &Ps[r * ATT_PS_STRIDE];
        const float* vb = &Vs[c * 32];
#pragma unroll 4
        for (int k = 0; k < 64; k++) {
            const float p = pr[k];
            const float* vr = vb + k * ATT_QS_STRIDE;
#pragma unroll
            for (int d4 = 0; d4 < 8; d4++) {
                const float4 vv = *(const float4*)(vr + (d4 << 2));
                o[d4 * 4 + 0] += p * vv.x;
                o[d4 * 4 + 1] += p * vv.y;
                o[d4 * 4 + 2] += p * vv.z;
                o[d4 * 4 + 3] += p * vv.w;
            }
        }
        __syncthreads();   // done with Ks/Vs/Ps before next tile overwrites
    }

    // Normalize and write: att[(b*SEQ + q), h*128 + c*32 ..]
    const float inv = 1.f / l;
    float* outp = att + ((size_t)b * SEQ + q0 + r) * D_MODEL + h * HD + c * 32;
#pragma unroll
    for (int d4 = 0; d4 < 8; d4++) {
        float4 ov;
        ov.x = o[d4 * 4 + 0] * inv;
        ov.y = o[d4 * 4 + 1] * inv;
        ov.z = o[d4 * 4 + 2] * inv;
        ov.w = o[d4 * 4 + 3] * inv;
        *(float4*)(outp + (d4 << 2)) = ov;
    }
}

// ---------------------------------------------------------------------------
// Launch: qkv GEMM -> flash attention -> out GEMM. Graph-capturable (kernel
// launches + attribute/symbol lookups only; no alloc, no sync, no memcpy).
// ---------------------------------------------------------------------------
extern "C" void kernel_launch(void* const* d_in, const int* in_sizes, int n_in,
                              void* d_out, int out_size)
{
    const float* x     = (const float*)d_in[0];
    const float* W_qkv = (const float*)d_in[1];
    const float* b_qkv = (const float*)d_in[2];
    const float* W_out = (const float*)d_in[3];
    const float* b_out = (const float*)d_in[4];
    float* y = (float*)d_out;

    float* qkv = nullptr;
    float* att = nullptr;
    cudaGetSymbolAddress((void**)&qkv, g_qkv);
    cudaGetSymbolAddress((void**)&att, g_att);

    // Opt in to >48KB dynamic smem for the attention kernel (idempotent).
    cudaFuncSetAttribute(attn_kernel,
                         cudaFuncAttributeMaxDynamicSharedMemorySize,
                         ATT_SMEM_BYTES);

    // 1) qkv = x @ W_qkv + b_qkv     (4096 x 6144, K=2048)
    sgemm128<<<dim3(QKV_N / 128, MROWS / 128), 256>>>(
        x, W_qkv, b_qkv, qkv, MROWS, QKV_N, D_MODEL);

    // 2) causal flash attention -> att (4096 x 2048, head-contiguous)
    attn_kernel<<<dim3(SEQ / 64, BATCH * NH), 256, ATT_SMEM_BYTES>>>(qkv, att);

    // 3) y = att @ W_out + b_out     (4096 x 2048, K=2048)
    sgemm128<<<dim3(D_MODEL / 128, MROWS / 128), 256>>>(
        att, W_out, b_out, y, MROWS, D_MODEL, D_MODEL);
}

// round 7
// speedup vs baseline: 1.1597x; 1.1597x over previous
#include <cuda_runtime.h>
#include <cuda_bf16.h>
#include <cstdint>
#include <cstddef>

// Problem constants
#define D_MODEL 2048
#define SEQ     2048
#define BATCH   2
#define NH      16
#define HD      128
#define MROWS   (BATCH * SEQ)          // 4096
#define QKV_N   (3 * D_MODEL)          // 6144

// ---------------------------------------------------------------------------
// Scratch (allocation-guard safe: __device__ globals)
// ---------------------------------------------------------------------------
__device__ float g_qkv[(size_t)MROWS * QKV_N];    // fp32 qkv
__device__ float g_att[(size_t)MROWS * D_MODEL];  // fp32 attention out
__device__ __nv_bfloat16 g_xh[(size_t)MROWS * D_MODEL];
__device__ __nv_bfloat16 g_xl[(size_t)MROWS * D_MODEL];
__device__ __nv_bfloat16 g_ah[(size_t)MROWS * D_MODEL];
__device__ __nv_bfloat16 g_al[(size_t)MROWS * D_MODEL];
__device__ __nv_bfloat16 g_wqTh[(size_t)QKV_N * D_MODEL];   // [N=6144][K=2048]
__device__ __nv_bfloat16 g_wqTl[(size_t)QKV_N * D_MODEL];
__device__ __nv_bfloat16 g_woTh[(size_t)D_MODEL * D_MODEL]; // [N=2048][K=2048]
__device__ __nv_bfloat16 g_woTl[(size_t)D_MODEL * D_MODEL];

// Unified dynamic smem (same extern decl for all kernels in this TU)
extern __shared__ char dynsmem[];

// ---------------------------------------------------------------------------
// Portable PTX wrappers (sm_80-level: valid at compute_103 — NO tcgen05/"a" ops)
// ---------------------------------------------------------------------------
__device__ __forceinline__ uint32_t smem_u32(const void* p) {
    uint32_t a;
    asm("{ .reg .u64 t; cvta.to.shared.u64 t, %1; cvt.u32.u64 %0, t; }"
        : "=r"(a) : "l"(p));
    return a;
}
__device__ __forceinline__ void cpa16(uint32_t saddr, const void* g) {
    asm volatile("cp.async.cg.shared.global [%0], [%1], 16;" :: "r"(saddr), "l"(g));
}
#define CP_COMMIT() asm volatile("cp.async.commit_group;" ::: "memory")
#define CP_WAIT0()  asm volatile("cp.async.wait_group 0;" ::: "memory")

__device__ __forceinline__ void ldsm4(uint32_t* r, uint32_t a) {
    asm volatile("ldmatrix.sync.aligned.m8n8.x4.shared.b16 {%0,%1,%2,%3}, [%4];"
        : "=r"(r[0]), "=r"(r[1]), "=r"(r[2]), "=r"(r[3]) : "r"(a));
}
__device__ __forceinline__ void mma16816(float* d, const uint32_t* a,
                                         uint32_t b0, uint32_t b1) {
    asm volatile(
        "mma.sync.aligned.m16n8k16.row.col.f32.bf16.bf16.f32 "
        "{%0,%1,%2,%3}, {%4,%5,%6,%7}, {%8,%9}, {%0,%1,%2,%3};"
        : "+f"(d[0]), "+f"(d[1]), "+f"(d[2]), "+f"(d[3])
        : "r"(a[0]), "r"(a[1]), "r"(a[2]), "r"(a[3]), "r"(b0), "r"(b1));
}

// ---------------------------------------------------------------------------
// Split-fp32 -> (bf16 hi, bf16 lo) conversions
// ---------------------------------------------------------------------------
__global__ __launch_bounds__(256) void convert_split(
    const float* __restrict__ in, __nv_bfloat16* __restrict__ ho,
    __nv_bfloat16* __restrict__ lo, int n4)
{
    int i = blockIdx.x * 256 + threadIdx.x;
    if (i >= n4) return;
    const float4 v = ((const float4*)in)[i];
    __nv_bfloat16 h[4], l[4];
    float vv[4] = {v.x, v.y, v.z, v.w};
#pragma unroll
    for (int j = 0; j < 4; j++) {
        h[j] = __float2bfloat16(vv[j]);
        l[j] = __float2bfloat16(vv[j] - __bfloat162float(h[j]));
    }
    ((uint2*)ho)[i] = *(uint2*)h;
    ((uint2*)lo)[i] = *(uint2*)l;
}

// W[K,N] fp32 -> Th/Tl[N,K] bf16 (transpose + split), 32x32 tiles
__global__ __launch_bounds__(256) void convert_split_T(
    const float* __restrict__ W, __nv_bfloat16* __restrict__ Th,
    __nv_bfloat16* __restrict__ Tl, int K, int N)
{
    __shared__ float tile[32][33];
    const int n0 = blockIdx.x * 32, k0 = blockIdx.y * 32;
    const int tx = threadIdx.x & 31, ty = threadIdx.x >> 5;  // 32 x 8
#pragma unroll
    for (int i = 0; i < 4; i++)
        tile[ty + 8 * i][tx] = W[(size_t)(k0 + ty + 8 * i) * N + n0 + tx];
    __syncthreads();
#pragma unroll
    for (int i = 0; i < 4; i++) {
        const float v = tile[tx][ty + 8 * i];
        const __nv_bfloat16 h = __float2bfloat16(v);
        const size_t o = (size_t)(n0 + ty + 8 * i) * K + k0 + tx;
        Th[o] = h;
        Tl[o] = __float2bfloat16(v - __bfloat162float(h));
    }
}

// ---------------------------------------------------------------------------
// Tensor-core GEMM via mma.sync (bf16 split emulating fp32):
//   C[M,N] = (Ah+Al)[M,K] @ (Bh+Bl)[N,K]^T + bias ~= AhBh + AhBl + AlBh
// CTA tile 128x128, BK=32, 256 threads (8 warps, 2x4), warp tile 64x32.
// cp.async double-buffered smem; 64B rows with XOR swizzle; ldmatrix feeds.
// ---------------------------------------------------------------------------
#define GM_TILE_B 8192              // 128 rows x 64B (32 bf16) per tile
#define GM_BUF_B  (4 * GM_TILE_B)   // Ah,Al,Bh,Bl
#define GM_SMEM_BYTES (2 * GM_BUF_B)  // 65536

__device__ __forceinline__ uint32_t gm_soff(int row, int c16) {
    return (uint32_t)(row * 64 + ((c16 ^ ((row >> 1) & 3)) << 4));
}

__global__ __launch_bounds__(256) void gemm_mma_split(
    const __nv_bfloat16* __restrict__ Ah, const __nv_bfloat16* __restrict__ Al,
    const __nv_bfloat16* __restrict__ Bh, const __nv_bfloat16* __restrict__ Bl,
    const float* __restrict__ bias, float* __restrict__ C,
    int M, int N, int K)
{
    const int t = threadIdx.x, wid = t >> 5, lane = t & 31;
    const int m0 = blockIdx.y * 128, n0 = blockIdx.x * 128;
    const int wm = (wid >> 2) * 64;     // warp m offset within tile
    const int wn = (wid & 3) * 32;      // warp n offset within tile

    const uint32_t sb = smem_u32(dynsmem);

    // gmem bases (bytes)
    const char* gA_h = (const char*)(Ah + (size_t)m0 * K);
    const char* gA_l = (const char*)(Al + (size_t)m0 * K);
    const char* gB_h = (const char*)(Bh + (size_t)n0 * K);
    const char* gB_l = (const char*)(Bl + (size_t)n0 * K);
    const size_t rowB = (size_t)K * 2;

    // load assignment: thread covers chunks (row, c16) for row = t>>2 and t>>2 + 64
    const int lr = t >> 2;
    const int lc = t & 3;
    const uint32_t so0 = gm_soff(lr, lc);
    const uint32_t so1 = gm_soff(lr + 64, lc);

    float acc[4][4][4];
#pragma unroll
    for (int i = 0; i < 4; i++)
#pragma unroll
        for (int j = 0; j < 4; j++)
#pragma unroll
            for (int e = 0; e < 4; e++) acc[i][j][e] = 0.f;

    // ---- prologue: stage slab 0 into buffer 0 ----
    {
        const size_t g0 = (size_t)lr * rowB + lc * 16;
        const size_t g1 = (size_t)(lr + 64) * rowB + lc * 16;
        const uint32_t b = sb;
        cpa16(b + 0 * GM_TILE_B + so0, gA_h + g0);
        cpa16(b + 0 * GM_TILE_B + so1, gA_h + g1);
        cpa16(b + 1 * GM_TILE_B + so0, gA_l + g0);
        cpa16(b + 1 * GM_TILE_B + so1, gA_l + g1);
        cpa16(b + 2 * GM_TILE_B + so0, gB_h + g0);
        cpa16(b + 2 * GM_TILE_B + so1, gB_h + g1);
        cpa16(b + 3 * GM_TILE_B + so0, gB_l + g0);
        cpa16(b + 3 * GM_TILE_B + so1, gB_l + g1);
        CP_COMMIT();
        CP_WAIT0();
        __syncthreads();
    }

    const int iters = K / 32;
    for (int it = 0; it < iters; it++) {
        const int cur = it & 1;
        const bool more = (it + 1) < iters;
        if (more) {   // stage next slab into other buffer (overlaps with MMAs)
            const int k0n = (it + 1) * 32;
            const size_t g0 = (size_t)lr * rowB + (size_t)k0n * 2 + lc * 16;
            const size_t g1 = (size_t)(lr + 64) * rowB + (size_t)k0n * 2 + lc * 16;
            const uint32_t b = sb + (cur ^ 1) * GM_BUF_B;
            cpa16(b + 0 * GM_TILE_B + so0, gA_h + g0);
            cpa16(b + 0 * GM_TILE_B + so1, gA_h + g1);
            cpa16(b + 1 * GM_TILE_B + so0, gA_l + g0);
            cpa16(b + 1 * GM_TILE_B + so1, gA_l + g1);
            cpa16(b + 2 * GM_TILE_B + so0, gB_h + g0);
            cpa16(b + 2 * GM_TILE_B + so1, gB_h + g1);
            cpa16(b + 3 * GM_TILE_B + so0, gB_l + g0);
            cpa16(b + 3 * GM_TILE_B + so1, gB_l + g1);
            CP_COMMIT();
        }

        const uint32_t bb = sb + cur * GM_BUF_B;
        const uint32_t sAh = bb + 0 * GM_TILE_B;
        const uint32_t sAl = bb + 1 * GM_TILE_B;
        const uint32_t sBh = bb + 2 * GM_TILE_B;
        const uint32_t sBl = bb + 3 * GM_TILE_B;

#pragma unroll
        for (int ks = 0; ks < 2; ks++) {
            const int arow = lane & 15;
            const int ac16 = ks * 2 + (lane >> 4);
            uint32_t ah[4][4], al[4][4];
#pragma unroll
            for (int mi = 0; mi < 4; mi++) {
                const uint32_t off = gm_soff(wm + mi * 16 + arow, ac16);
                ldsm4(ah[mi], sAh + off);
                ldsm4(al[mi], sAl + off);
            }
            uint32_t bh[4][2], bl[4][2];
#pragma unroll
            for (int g = 0; g < 2; g++) {
                const uint32_t off = gm_soff(wn + g * 16 + arow, ac16);
                uint32_t q[4];
                ldsm4(q, sBh + off);
                bh[2 * g][0] = q[0]; bh[2 * g][1] = q[2];
                bh[2 * g + 1][0] = q[1]; bh[2 * g + 1][1] = q[3];
                ldsm4(q, sBl + off);
                bl[2 * g][0] = q[0]; bl[2 * g][1] = q[2];
                bl[2 * g + 1][0] = q[1]; bl[2 * g + 1][1] = q[3];
            }
#pragma unroll
            for (int mi = 0; mi < 4; mi++)
#pragma unroll
                for (int nj = 0; nj < 4; nj++) {
                    mma16816(acc[mi][nj], ah[mi], bh[nj][0], bh[nj][1]);
                    mma16816(acc[mi][nj], ah[mi], bl[nj][0], bl[nj][1]);
                    mma16816(acc[mi][nj], al[mi], bh[nj][0], bh[nj][1]);
                }
        }

        if (more) CP_WAIT0();
        __syncthreads();
    }

    // ---- epilogue: fragments -> gmem with bias (fp32) ----
    const int gr = lane >> 2;
    const int gc = (lane & 3) * 2;
#pragma unroll
    for (int nj = 0; nj < 4; nj++) {
        const int col = n0 + wn + nj * 8 + gc;
        const float2 bb2 = *(const float2*)(bias + col);
#pragma unroll
        for (int mi = 0; mi < 4; mi++) {
            const int row = m0 + wm + mi * 16 + gr;
            float2 v0, v1;
            v0.x = acc[mi][nj][0] + bb2.x;
            v0.y = acc[mi][nj][1] + bb2.y;
            v1.x = acc[mi][nj][2] + bb2.x;
            v1.y = acc[mi][nj][3] + bb2.y;
            *(float2*)(C + (size_t)row * N + col)       = v0;
            *(float2*)(C + (size_t)(row + 8) * N + col) = v1;
        }
    }
}

// ---------------------------------------------------------------------------
// Causal flash attention, fp32 (unchanged from passing Round-2 kernel).
// ---------------------------------------------------------------------------
#define ATT_QS_STRIDE 132
#define ATT_PS_STRIDE 68
#define ATT_SMEM_FLOATS (3 * 64 * ATT_QS_STRIDE + 64 * ATT_PS_STRIDE)
#define ATT_SMEM_BYTES  (ATT_SMEM_FLOATS * 4)

__global__ __launch_bounds__(256) void attn_kernel(
    const float* __restrict__ qkv, float* __restrict__ att)
{
    float* smemf = (float*)dynsmem;
    float* Qs = smemf;
    float* Ks = Qs + 64 * ATT_QS_STRIDE;
    float* Vs = Ks + 64 * ATT_QS_STRIDE;
    float* Ps = Vs + 64 * ATT_QS_STRIDE;

    const int t = threadIdx.x;
    const int r = t >> 2;
    const int c = t & 3;
    const int bh = blockIdx.y;
    const int b  = bh >> 4;
    const int h  = bh & 15;
    const int q0 = blockIdx.x * 64;

    const float* base = qkv + (size_t)b * SEQ * QKV_N + (size_t)h * HD;

    for (int i = t; i < 64 * 32; i += 256) {
        const int row = i >> 5;
        const int col = (i & 31) << 2;
        const float4 v = *(const float4*)(base + (size_t)(q0 + row) * QKV_N + col);
        *(float4*)&Qs[row * ATT_QS_STRIDE + col] = v;
    }

    float o[32];
#pragma unroll
    for (int i = 0; i < 32; i++) o[i] = 0.f;
    float m = -1e30f, l = 0.f;

    const float scale = 0.08838834764831845f;
    const int ntiles = blockIdx.x + 1;

    for (int kt = 0; kt < ntiles; kt++) {
        for (int i = t; i < 64 * 32; i += 256) {
            const int row = i >> 5;
            const int col = (i & 31) << 2;
            const size_t roff = (size_t)(kt * 64 + row) * QKV_N;
            const float4 kv = *(const float4*)(base + roff + D_MODEL + col);
            const float4 vv = *(const float4*)(base + roff + 2 * D_MODEL + col);
            *(float4*)&Ks[row * ATT_QS_STRIDE + col] = kv;
            *(float4*)&Vs[row * ATT_QS_STRIDE + col] = vv;
        }
        __syncthreads();

        float s[16];
#pragma unroll
        for (int j = 0; j < 16; j++) s[j] = 0.f;
        const float* qrow = &Qs[r * ATT_QS_STRIDE];
        const float* krow0 = &Ks[(c * 16) * ATT_QS_STRIDE];
#pragma unroll 4
        for (int d = 0; d < HD; d += 4) {
            const float4 qv = *(const float4*)(qrow + d);
#pragma unroll
            for (int j = 0; j < 16; j++) {
                const float4 kv = *(const float4*)(krow0 + j * ATT_QS_STRIDE + d);
                s[j] += qv.x * kv.x + qv.y * kv.y + qv.z * kv.z + qv.w * kv.w;
            }
        }

        const int qg = q0 + r;
#pragma unroll
        for (int j = 0; j < 16; j++) {
            const int kg = kt * 64 + c * 16 + j;
            s[j] = (kg > qg) ? -1e30f : s[j] * scale;
        }

        float mt = s[0];
#pragma unroll
        for (int j = 1; j < 16; j++) mt = fmaxf(mt, s[j]);
        mt = fmaxf(mt, __shfl_xor_sync(0xffffffffu, mt, 1));
        mt = fmaxf(mt, __shfl_xor_sync(0xffffffffu, mt, 2));

        const float mnew  = fmaxf(m, mt);
        const float alpha = __expf(m - mnew);

        float lsum = 0.f;
        float* prow = &Ps[r * ATT_PS_STRIDE + c * 16];
#pragma unroll
        for (int j = 0; j < 16; j++) {
            const float p = __expf(s[j] - mnew);
            lsum += p;
            prow[j] = p;
        }
        lsum += __shfl_xor_sync(0xffffffffu, lsum, 1);
        lsum += __shfl_xor_sync(0xffffffffu, lsum, 2);

        l = l * alpha + lsum;
        m = mnew;
#pragma unroll
        for (int i = 0; i < 32; i++) o[i] *= alpha;

        __syncthreads();

        const float* pr = &Ps[r * ATT_PS_STRIDE];
        const float* vb = &Vs[c * 32];
#pragma unroll 4
        for (int k = 0; k < 64; k++) {
            const float p = pr[k];
            const float* vr = vb + k * ATT_QS_STRIDE;
#pragma unroll
            for (int d4 = 0; d4 < 8; d4++) {
                const float4 vv = *(const float4*)(vr + (d4 << 2));
                o[d4 * 4 + 0] += p * vv.x;
                o[d4 * 4 + 1] += p * vv.y;
                o[d4 * 4 + 2] += p * vv.z;
                o[d4 * 4 + 3] += p * vv.w;
            }
        }
        __syncthreads();
    }

    const float inv = 1.f / l;
    float* outp = att + ((size_t)b * SEQ + q0 + r) * D_MODEL + h * HD + c * 32;
#pragma unroll
    for (int d4 = 0; d4 < 8; d4++) {
        float4 ov;
        ov.x = o[d4 * 4 + 0] * inv;
        ov.y = o[d4 * 4 + 1] * inv;
        ov.z = o[d4 * 4 + 2] * inv;
        ov.w = o[d4 * 4 + 3] * inv;
        *(float4*)(outp + (d4 << 2)) = ov;
    }
}

// ---------------------------------------------------------------------------
// Launch. Graph-capturable: kernel launches + symbol/attr queries only.
// ---------------------------------------------------------------------------
extern "C" void kernel_launch(void* const* d_in, const int* in_sizes, int n_in,
                              void* d_out, int out_size)
{
    const float* x     = (const float*)d_in[0];
    const float* W_qkv = (const float*)d_in[1];
    const float* b_qkv = (const float*)d_in[2];
    const float* W_out = (const float*)d_in[3];
    const float* b_out = (const float*)d_in[4];
    float* y = (float*)d_out;

    float *qkv, *att;
    __nv_bfloat16 *xh, *xl, *ah, *al, *wqTh, *wqTl, *woTh, *woTl;
    cudaGetSymbolAddress((void**)&qkv,  g_qkv);
    cudaGetSymbolAddress((void**)&att,  g_att);
    cudaGetSymbolAddress((void**)&xh,   g_xh);
    cudaGetSymbolAddress((void**)&xl,   g_xl);
    cudaGetSymbolAddress((void**)&ah,   g_ah);
    cudaGetSymbolAddress((void**)&al,   g_al);
    cudaGetSymbolAddress((void**)&wqTh, g_wqTh);
    cudaGetSymbolAddress((void**)&wqTl, g_wqTl);
    cudaGetSymbolAddress((void**)&woTh, g_woTh);
    cudaGetSymbolAddress((void**)&woTl, g_woTl);

    cudaFuncSetAttribute(attn_kernel,
                         cudaFuncAttributeMaxDynamicSharedMemorySize, ATT_SMEM_BYTES);
    cudaFuncSetAttribute(gemm_mma_split,
                         cudaFuncAttributeMaxDynamicSharedMemorySize, GM_SMEM_BYTES);

    const int n4x = MROWS * D_MODEL / 4;

    // split-convert activations and weights
    convert_split<<<(n4x + 255) / 256, 256>>>(x, xh, xl, n4x);
    convert_split_T<<<dim3(QKV_N / 32, D_MODEL / 32), 256>>>(W_qkv, wqTh, wqTl, D_MODEL, QKV_N);
    convert_split_T<<<dim3(D_MODEL / 32, D_MODEL / 32), 256>>>(W_out, woTh, woTl, D_MODEL, D_MODEL);

    // 1) qkv = x @ W_qkv + b_qkv   (tensor cores via mma.sync, split-bf16)
    gemm_mma_split<<<dim3(QKV_N / 128, MROWS / 128), 256, GM_SMEM_BYTES>>>(
        xh, xl, wqTh, wqTl, b_qkv, qkv, MROWS, QKV_N, D_MODEL);

    // 2) causal flash attention (fp32 SIMT)
    attn_kernel<<<dim3(SEQ / 64, BATCH * NH), 256, ATT_SMEM_BYTES>>>(qkv, att);

    // 3) y = att @ W_out + b_out   (tensor cores via mma.sync, split-bf16)
    convert_split<<<(n4x + 255) / 256, 256>>>(att, ah, al, n4x);
    gemm_mma_split<<<dim3(D_MODEL / 128, MROWS / 128), 256, GM_SMEM_BYTES>>>(
        ah, al, woTh, woTl, b_out, y, MROWS, D_MODEL, D_MODEL);
}